// round 2
// baseline (speedup 1.0000x reference)
#include <cuda_runtime.h>
#include <math.h>

// Problem constants
#define BB 8
#define LL 128
#define DD 512
#define EE 64
#define HH 8
#define CC 64
#define BL (BB*LL)   // 1024

// Scratch (static device arrays — no allocation allowed)
__device__ float dQ[BL*DD];              // 2 MB  x@Wq, layout [r][d]
__device__ float dKV[BL*DD];             // 2 MB  x@Wkv
__device__ float dG[BL*HH*EE];           // 2 MB  g[r][h][e] = We_h^T q_h
__device__ float dS1[BB*HH*LL*LL];       // 4 MB  q·kv scores [bh][q][k]
__device__ float dALPHA[BB*HH*LL*LL];    // 4 MB  softmaxed attention
__device__ float dWsum[BB*HH*LL*EE];     // 2 MB  sum_k alpha*e  [bh*128+q][e]
__device__ float dATTN[BL*DD];           // 2 MB  attention output (B,L,D)
__device__ float dFFN[BL*DD];            // 2 MB  pre-layernorm FFN output

// ---------------------------------------------------------------------------
// Generic 64x64 tiled fp32 GEMM (row-major), K-tile 32, 256 threads, 4x4/thread.
// blockIdx.z selects (B0,C0) or (B1,C1) so both projections run in one launch.
// ---------------------------------------------------------------------------
__global__ __launch_bounds__(256) void gemm64_kernel(
    const float* __restrict__ A,
    const float* __restrict__ B0, float* __restrict__ C0,
    const float* __restrict__ B1, float* __restrict__ C1,
    const float* __restrict__ bias,
    int M, int N, int K)
{
    const float* Bm = (blockIdx.z == 0) ? B0 : B1;
    float*       Cm = (blockIdx.z == 0) ? C0 : C1;

    __shared__ float Ast[32 * 65];   // [kk][m], padded stride 65
    __shared__ float Bs [32 * 64];   // [kk][n]

    const int t  = threadIdx.x;
    const int tx = t & 15, ty = t >> 4;
    const int m0 = blockIdx.y * 64, n0 = blockIdx.x * 64;

    float acc[4][4] = {};

    for (int k0 = 0; k0 < K; k0 += 32) {
        // A tile: 64 m x 32 k  (512 float4, 2 per thread), stored transposed
        #pragma unroll
        for (int r = 0; r < 2; r++) {
            int idx = t + r * 256;
            int m   = idx >> 3;
            int k4  = (idx & 7) << 2;
            float4 v = *(const float4*)(A + (size_t)(m0 + m) * K + k0 + k4);
            Ast[(k4 + 0) * 65 + m] = v.x;
            Ast[(k4 + 1) * 65 + m] = v.y;
            Ast[(k4 + 2) * 65 + m] = v.z;
            Ast[(k4 + 3) * 65 + m] = v.w;
        }
        // B tile: 32 k x 64 n
        #pragma unroll
        for (int r = 0; r < 2; r++) {
            int idx = t + r * 256;
            int kk  = idx >> 4;
            int n4  = (idx & 15) << 2;
            float4 v = *(const float4*)(Bm + (size_t)(k0 + kk) * N + n0 + n4);
            *(float4*)(Bs + kk * 64 + n4) = v;
        }
        __syncthreads();

        #pragma unroll
        for (int kk = 0; kk < 32; kk++) {
            float a[4], b[4];
            #pragma unroll
            for (int i = 0; i < 4; i++) a[i] = Ast[kk * 65 + ty + 16 * i];
            #pragma unroll
            for (int j = 0; j < 4; j++) b[j] = Bs[kk * 64 + tx + 16 * j];
            #pragma unroll
            for (int i = 0; i < 4; i++)
                #pragma unroll
                for (int j = 0; j < 4; j++)
                    acc[i][j] += a[i] * b[j];
        }
        __syncthreads();
    }

    #pragma unroll
    for (int i = 0; i < 4; i++) {
        int m = m0 + ty + 16 * i;
        #pragma unroll
        for (int j = 0; j < 4; j++) {
            int n = n0 + tx + 16 * j;
            float v = acc[i][j];
            if (bias) v += bias[n];
            Cm[(size_t)m * N + n] = v;
        }
    }
}

// ---------------------------------------------------------------------------
// g[r][h][e] = sum_c Q[r, h*64+c] * We[e, h*64+c]
// grid: (BL/64, H), 256 threads, 64x64 output tile, K=64 fully resident
// ---------------------------------------------------------------------------
__global__ __launch_bounds__(256) void g_kernel(const float* __restrict__ We)
{
    __shared__ float Qs[64 * 65];   // [m][c]
    __shared__ float Ws[64 * 65];   // [e][c]

    const int t  = threadIdx.x;
    const int tx = t & 15, ty = t >> 4;
    const int r0 = blockIdx.x * 64;
    const int h  = blockIdx.y;

    #pragma unroll
    for (int r = 0; r < 4; r++) {
        int idx = t + r * 256;       // 0..1023 float4
        int m   = idx >> 4;          // 0..63
        int c4  = (idx & 15) << 2;
        float4 q = *(const float4*)(dQ + (size_t)(r0 + m) * DD + h * 64 + c4);
        Qs[m * 65 + c4 + 0] = q.x; Qs[m * 65 + c4 + 1] = q.y;
        Qs[m * 65 + c4 + 2] = q.z; Qs[m * 65 + c4 + 3] = q.w;
        float4 w = *(const float4*)(We + (size_t)m * DD + h * 64 + c4);
        Ws[m * 65 + c4 + 0] = w.x; Ws[m * 65 + c4 + 1] = w.y;
        Ws[m * 65 + c4 + 2] = w.z; Ws[m * 65 + c4 + 3] = w.w;
    }
    __syncthreads();

    float acc[4][4] = {};
    #pragma unroll
    for (int c = 0; c < 64; c++) {
        float a[4], b[4];
        #pragma unroll
        for (int i = 0; i < 4; i++) a[i] = Qs[(ty + 16 * i) * 65 + c];
        #pragma unroll
        for (int j = 0; j < 4; j++) b[j] = Ws[(tx + 16 * j) * 65 + c];
        #pragma unroll
        for (int i = 0; i < 4; i++)
            #pragma unroll
            for (int j = 0; j < 4; j++)
                acc[i][j] += a[i] * b[j];
    }

    #pragma unroll
    for (int i = 0; i < 4; i++) {
        int m = r0 + ty + 16 * i;
        #pragma unroll
        for (int j = 0; j < 4; j++) {
            int e = tx + 16 * j;
            dG[((size_t)m * HH + h) * EE + e] = acc[i][j];
        }
    }
}

// ---------------------------------------------------------------------------
// S1[bh][q][k] = sum_c Q_h[b,q,c] * KV_h[b,k,c]    (batched over bh, 64 blocks)
// 128x128 output, 256 threads, 8x8 per thread, c-tiles of 32
// ---------------------------------------------------------------------------
__global__ __launch_bounds__(256) void s1_kernel()
{
    __shared__ float Qs[128 * 32];   // [m][cc]
    __shared__ float Ks[128 * 33];   // [n][cc], padded

    const int bh = blockIdx.x;
    const int b  = bh >> 3, h = bh & 7;
    const int t  = threadIdx.x;
    const int tx = t & 15, ty = t >> 4;

    float acc[8][8] = {};

    for (int c0 = 0; c0 < 64; c0 += 32) {
        #pragma unroll
        for (int r = 0; r < 4; r++) {
            int idx = t + r * 256;       // 0..1023 float4
            int m   = idx >> 3;          // 0..127
            int c4  = (idx & 7) << 2;
            float4 q = *(const float4*)(dQ + (size_t)(b * LL + m) * DD + h * 64 + c0 + c4);
            *(float4*)(Qs + m * 32 + c4) = q;
            float4 k = *(const float4*)(dKV + (size_t)(b * LL + m) * DD + h * 64 + c0 + c4);
            Ks[m * 33 + c4 + 0] = k.x; Ks[m * 33 + c4 + 1] = k.y;
            Ks[m * 33 + c4 + 2] = k.z; Ks[m * 33 + c4 + 3] = k.w;
        }
        __syncthreads();

        #pragma unroll
        for (int cc = 0; cc < 32; cc++) {
            float a[8], bb[8];
            #pragma unroll
            for (int i = 0; i < 8; i++) a[i]  = Qs[(ty + 16 * i) * 32 + cc];
            #pragma unroll
            for (int j = 0; j < 8; j++) bb[j] = Ks[(tx + 16 * j) * 33 + cc];
            #pragma unroll
            for (int i = 0; i < 8; i++)
                #pragma unroll
                for (int j = 0; j < 8; j++)
                    acc[i][j] += a[i] * bb[j];
        }
        __syncthreads();
    }

    #pragma unroll
    for (int i = 0; i < 8; i++) {
        int m = ty + 16 * i;
        #pragma unroll
        for (int j = 0; j < 8; j++) {
            int n = tx + 16 * j;
            dS1[((size_t)bh * LL + m) * LL + n] = acc[i][j];
        }
    }
}

// ---------------------------------------------------------------------------
// Per (b,q): scores = (S1 + e·g)/8 -> leaky -> mask -> softmax -> alpha;
//            Wsum[e] = sum_k alpha_k * e[k][e].   1024 blocks x 128 threads.
// ---------------------------------------------------------------------------
__global__ __launch_bounds__(128) void softmax_kernel(
    const float* __restrict__ eptr, const int* __restrict__ adj)
{
    __shared__ float es[128 * 65];   // e tile [k][j], padded
    __shared__ float gs[64];
    __shared__ float sc[128];
    __shared__ float red[4];
    __shared__ float wtmp[128];

    const int bq = blockIdx.x;        // b*128 + q
    const int b  = bq >> 7, q = bq & 127;
    const int t  = threadIdx.x;
    const int lane = t & 31, warp = t >> 5;

    // load e[b,q,:,:]  (128x64 floats)
    #pragma unroll
    for (int r = 0; r < 16; r++) {
        int idx = t + r * 128;        // 0..2047 float4
        int k   = idx >> 4;
        int j4  = (idx & 15) << 2;
        float4 v = *(const float4*)(eptr + ((size_t)bq * LL + k) * EE + j4);
        es[k * 65 + j4 + 0] = v.x; es[k * 65 + j4 + 1] = v.y;
        es[k * 65 + j4 + 2] = v.z; es[k * 65 + j4 + 3] = v.w;
    }
    const int adjv = adj[(size_t)bq * LL + t];

    for (int h = 0; h < HH; h++) {
        __syncthreads();
        if (t < 64) gs[t] = dG[((size_t)bq * HH + h) * EE + t];
        __syncthreads();

        // score for k = t
        float dot = 0.f;
        #pragma unroll
        for (int j = 0; j < 64; j++) dot += es[t * 65 + j] * gs[j];
        float s = (dS1[(((size_t)(b * HH + h)) * LL + q) * LL + t] + dot) * 0.125f;
        s = (s > 0.f) ? s : 0.2f * s;
        if (adjv == 0) s = -1e9f;

        // row max
        float mx = s;
        #pragma unroll
        for (int o = 16; o > 0; o >>= 1) mx = fmaxf(mx, __shfl_xor_sync(0xffffffff, mx, o));
        if (lane == 0) red[warp] = mx;
        __syncthreads();
        mx = fmaxf(fmaxf(red[0], red[1]), fmaxf(red[2], red[3]));
        __syncthreads();

        float p = expf(s - mx);
        float su = p;
        #pragma unroll
        for (int o = 16; o > 0; o >>= 1) su += __shfl_xor_sync(0xffffffff, su, o);
        if (lane == 0) red[warp] = su;
        __syncthreads();
        float total = red[0] + red[1] + red[2] + red[3];
        float pk = p / total;
        sc[t] = pk;
        dALPHA[(((size_t)(b * HH + h)) * LL + q) * LL + t] = pk;
        __syncthreads();

        // Wsum: 2 threads per e
        {
            int ei = t & 63, half = t >> 6;
            float acc = 0.f;
            #pragma unroll
            for (int k = 0; k < 64; k++) {
                int kk = half * 64 + k;
                acc += sc[kk] * es[kk * 65 + ei];
            }
            wtmp[t] = acc;
            __syncthreads();
            if (t < 64)
                dWsum[(((size_t)(b * HH + h)) * LL + q) * EE + t] = wtmp[t] + wtmp[64 + t];
        }
    }
}

// ---------------------------------------------------------------------------
// ATTN[b,q,h*64+c] = alpha[bh,q,:] @ KV_h[b,:,c]  +  Wsum[bh,q,:] @ We_h[:,c]
// One 192-deep GEMM per (bh, m-half). grid (64,2), 256 threads, 4x4/thread.
// ---------------------------------------------------------------------------
__global__ __launch_bounds__(256) void attn_kernel(const float* __restrict__ We)
{
    __shared__ float As[64 * 32];   // [m][kk]
    __shared__ float Bs[32 * 64];   // [kk][n]

    const int bh = blockIdx.x, mh = blockIdx.y;
    const int b  = bh >> 3, h = bh & 7;
    const int t  = threadIdx.x;
    const int tx = t & 15, ty = t >> 4;

    float acc[4][4] = {};

    for (int k0 = 0; k0 < 192; k0 += 32) {
        // A tile (alpha for k<128, Wsum for k>=128)
        #pragma unroll
        for (int r = 0; r < 2; r++) {
            int idx = t + r * 256;
            int m   = idx >> 3;
            int k4  = (idx & 7) << 2;
            size_t row = (size_t)bh * LL + mh * 64 + m;
            float4 v;
            if (k0 < 128) v = *(const float4*)(dALPHA + row * LL + k0 + k4);
            else          v = *(const float4*)(dWsum  + row * EE + (k0 - 128) + k4);
            *(float4*)(As + m * 32 + k4) = v;
        }
        // B tile (KV rows for k<128, We rows for k>=128)
        #pragma unroll
        for (int r = 0; r < 2; r++) {
            int idx = t + r * 256;
            int kk  = idx >> 4;
            int n4  = (idx & 15) << 2;
            int kg  = k0 + kk;
            float4 v;
            if (kg < 128) v = *(const float4*)(dKV + (size_t)(b * LL + kg) * DD + h * 64 + n4);
            else          v = *(const float4*)(We + (size_t)(kg - 128) * DD + h * 64 + n4);
            *(float4*)(Bs + kk * 64 + n4) = v;
        }
        __syncthreads();

        #pragma unroll
        for (int kk = 0; kk < 32; kk++) {
            float a[4], bb[4];
            #pragma unroll
            for (int i = 0; i < 4; i++) a[i]  = As[(ty + 16 * i) * 32 + kk];
            #pragma unroll
            for (int j = 0; j < 4; j++) bb[j] = Bs[kk * 64 + tx + 16 * j];
            #pragma unroll
            for (int i = 0; i < 4; i++)
                #pragma unroll
                for (int j = 0; j < 4; j++)
                    acc[i][j] += a[i] * bb[j];
        }
        __syncthreads();
    }

    #pragma unroll
    for (int i = 0; i < 4; i++) {
        int m = mh * 64 + ty + 16 * i;
        #pragma unroll
        for (int j = 0; j < 4; j++) {
            int n = tx + 16 * j;
            dATTN[((size_t)b * LL + m) * DD + h * 64 + n] = acc[i][j];
        }
    }
}

// ---------------------------------------------------------------------------
// LayerNorm + ReLU per row of 512. 1024 blocks x 256 threads.
// ---------------------------------------------------------------------------
__global__ __launch_bounds__(256) void ln_kernel(
    const float* __restrict__ gamma, const float* __restrict__ beta,
    float* __restrict__ out)
{
    const int r = blockIdx.x;
    const int t = threadIdx.x;
    const int lane = t & 31, warp = t >> 5;

    float v0 = dFFN[(size_t)r * DD + t];
    float v1 = dFFN[(size_t)r * DD + 256 + t];
    float s  = v0 + v1;
    float sq = v0 * v0 + v1 * v1;

    __shared__ float rs[8], rq[8];
    __shared__ float mu_s, rstd_s;
    #pragma unroll
    for (int o = 16; o > 0; o >>= 1) {
        s  += __shfl_xor_sync(0xffffffff, s, o);
        sq += __shfl_xor_sync(0xffffffff, sq, o);
    }
    if (lane == 0) { rs[warp] = s; rq[warp] = sq; }
    __syncthreads();
    if (t == 0) {
        float S = 0.f, Q2 = 0.f;
        #pragma unroll
        for (int w = 0; w < 8; w++) { S += rs[w]; Q2 += rq[w]; }
        float mu  = S / 512.f;
        float var = Q2 / 512.f - mu * mu;
        mu_s = mu;
        rstd_s = rsqrtf(var + 1e-5f);
    }
    __syncthreads();
    float mu = mu_s, rstd = rstd_s;

    float y0 = (v0 - mu) * rstd * gamma[t]       + beta[t];
    float y1 = (v1 - mu) * rstd * gamma[256 + t] + beta[256 + t];
    out[(size_t)r * DD + t]       = fmaxf(y0, 0.f);
    out[(size_t)r * DD + 256 + t] = fmaxf(y1, 0.f);
}

// ---------------------------------------------------------------------------
extern "C" void kernel_launch(void* const* d_in, const int* in_sizes, int n_in,
                              void* d_out, int out_size)
{
    const float* x     = (const float*)d_in[0];
    const int*   adj   = (const int*)  d_in[1];
    const float* e     = (const float*)d_in[2];
    const float* Wq    = (const float*)d_in[3];
    const float* Wkv   = (const float*)d_in[4];
    const float* We    = (const float*)d_in[5];
    const float* Wf    = (const float*)d_in[6];
    const float* bf    = (const float*)d_in[7];
    const float* gamma = (const float*)d_in[8];
    const float* beta  = (const float*)d_in[9];
    float* out = (float*)d_out;

    float *pQ, *pKV, *pATTN, *pFFN;
    cudaGetSymbolAddress((void**)&pQ,    dQ);
    cudaGetSymbolAddress((void**)&pKV,   dKV);
    cudaGetSymbolAddress((void**)&pATTN, dATTN);
    cudaGetSymbolAddress((void**)&pFFN,  dFFN);

    // 1. Q = x@Wq, KV = x@Wkv (one launch, z selects)
    gemm64_kernel<<<dim3(DD/64, BL/64, 2), 256>>>(x, Wq, pQ, Wkv, pKV, nullptr,
                                                  BL, DD, DD);
    // 2. g = We_h^T q_h
    g_kernel<<<dim3(BL/64, HH), 256>>>(We);
    // 3. S1 = Q_h @ KV_h^T (batched)
    s1_kernel<<<BB*HH, 256>>>();
    // 4. softmax + alpha-weighted e reduction
    softmax_kernel<<<BL, 128>>>(e, adj);
    // 5. attention output (alpha@KV + Wsum@We_h)
    attn_kernel<<<dim3(BB*HH, 2), 256>>>(We);
    // 6. FFN GEMM with bias
    gemm64_kernel<<<dim3(DD/64, BL/64, 1), 256>>>(pATTN, Wf, pFFN, nullptr, nullptr,
                                                  bf, BL, DD, DD);
    // 7. LayerNorm + ReLU -> d_out
    ln_kernel<<<BL, 256>>>(gamma, beta, out);
}

// round 3
// speedup vs baseline: 1.0478x; 1.0478x over previous
#include <cuda_runtime.h>
#include <math.h>

// Problem constants
#define BB 8
#define LL 128
#define DD 512
#define EE 64
#define HH 8
#define CC 64
#define BL (BB*LL)   // 1024

// Scratch (static device arrays — no allocation allowed)
__device__ float dQ[BL*DD];              // 2 MB  x@Wq, layout [r][d]
__device__ float dKV[BL*DD];             // 2 MB  x@Wkv
__device__ float dG[BL*HH*EE];           // 2 MB  g[r][h][e] = We_h^T q_h
__device__ float dS1[BB*HH*LL*LL];       // 4 MB  q·kv scores [bh][q][k]
__device__ float dALPHA[BB*HH*LL*LL];    // 4 MB  softmaxed attention
__device__ float dWsum[BB*HH*LL*EE];     // 2 MB  sum_k alpha*e  [bh*128+q][e]
__device__ float dATTN[BL*DD];           // 2 MB  attention output (B,L,D)
__device__ float dFFN[BL*DD];            // 2 MB  pre-layernorm FFN output

// ---------------------------------------------------------------------------
// Generic 64x64 tiled fp32 GEMM (row-major), K-tile 32, 256 threads, 4x4/thread.
// blockIdx.z selects (B0,C0) or (B1,C1) so both projections run in one launch.
// ---------------------------------------------------------------------------
__global__ __launch_bounds__(256) void gemm64_kernel(
    const float* __restrict__ A,
    const float* __restrict__ B0, float* __restrict__ C0,
    const float* __restrict__ B1, float* __restrict__ C1,
    const float* __restrict__ bias,
    int M, int N, int K)
{
    const float* Bm = (blockIdx.z == 0) ? B0 : B1;
    float*       Cm = (blockIdx.z == 0) ? C0 : C1;

    __shared__ float Ast[32 * 65];   // [kk][m], padded stride 65
    __shared__ float Bs [32 * 64];   // [kk][n]

    const int t  = threadIdx.x;
    const int tx = t & 15, ty = t >> 4;
    const int m0 = blockIdx.y * 64, n0 = blockIdx.x * 64;

    float acc[4][4] = {};

    for (int k0 = 0; k0 < K; k0 += 32) {
        // A tile: 64 m x 32 k  (512 float4, 2 per thread), stored transposed
        #pragma unroll
        for (int r = 0; r < 2; r++) {
            int idx = t + r * 256;
            int m   = idx >> 3;
            int k4  = (idx & 7) << 2;
            float4 v = *(const float4*)(A + (size_t)(m0 + m) * K + k0 + k4);
            Ast[(k4 + 0) * 65 + m] = v.x;
            Ast[(k4 + 1) * 65 + m] = v.y;
            Ast[(k4 + 2) * 65 + m] = v.z;
            Ast[(k4 + 3) * 65 + m] = v.w;
        }
        // B tile: 32 k x 64 n
        #pragma unroll
        for (int r = 0; r < 2; r++) {
            int idx = t + r * 256;
            int kk  = idx >> 4;
            int n4  = (idx & 15) << 2;
            float4 v = *(const float4*)(Bm + (size_t)(k0 + kk) * N + n0 + n4);
            *(float4*)(Bs + kk * 64 + n4) = v;
        }
        __syncthreads();

        #pragma unroll
        for (int kk = 0; kk < 32; kk++) {
            float a[4], b[4];
            #pragma unroll
            for (int i = 0; i < 4; i++) a[i] = Ast[kk * 65 + ty + 16 * i];
            #pragma unroll
            for (int j = 0; j < 4; j++) b[j] = Bs[kk * 64 + tx + 16 * j];
            #pragma unroll
            for (int i = 0; i < 4; i++)
                #pragma unroll
                for (int j = 0; j < 4; j++)
                    acc[i][j] += a[i] * b[j];
        }
        __syncthreads();
    }

    #pragma unroll
    for (int i = 0; i < 4; i++) {
        int m = m0 + ty + 16 * i;
        #pragma unroll
        for (int j = 0; j < 4; j++) {
            int n = n0 + tx + 16 * j;
            float v = acc[i][j];
            if (bias) v += bias[n];
            Cm[(size_t)m * N + n] = v;
        }
    }
}

// ---------------------------------------------------------------------------
// g[r][h][e] = sum_c Q[r, h*64+c] * We[e, h*64+c]
// grid: (BL/64, H), 256 threads, 64x64 output tile, K=64 fully resident
// ---------------------------------------------------------------------------
__global__ __launch_bounds__(256) void g_kernel(const float* __restrict__ We)
{
    __shared__ float Qs[64 * 65];   // [m][c]
    __shared__ float Ws[64 * 65];   // [e][c]

    const int t  = threadIdx.x;
    const int tx = t & 15, ty = t >> 4;
    const int r0 = blockIdx.x * 64;
    const int h  = blockIdx.y;

    #pragma unroll
    for (int r = 0; r < 4; r++) {
        int idx = t + r * 256;       // 0..1023 float4
        int m   = idx >> 4;          // 0..63
        int c4  = (idx & 15) << 2;
        float4 q = *(const float4*)(dQ + (size_t)(r0 + m) * DD + h * 64 + c4);
        Qs[m * 65 + c4 + 0] = q.x; Qs[m * 65 + c4 + 1] = q.y;
        Qs[m * 65 + c4 + 2] = q.z; Qs[m * 65 + c4 + 3] = q.w;
        float4 w = *(const float4*)(We + (size_t)m * DD + h * 64 + c4);
        Ws[m * 65 + c4 + 0] = w.x; Ws[m * 65 + c4 + 1] = w.y;
        Ws[m * 65 + c4 + 2] = w.z; Ws[m * 65 + c4 + 3] = w.w;
    }
    __syncthreads();

    float acc[4][4] = {};
    #pragma unroll
    for (int c = 0; c < 64; c++) {
        float a[4], b[4];
        #pragma unroll
        for (int i = 0; i < 4; i++) a[i] = Qs[(ty + 16 * i) * 65 + c];
        #pragma unroll
        for (int j = 0; j < 4; j++) b[j] = Ws[(tx + 16 * j) * 65 + c];
        #pragma unroll
        for (int i = 0; i < 4; i++)
            #pragma unroll
            for (int j = 0; j < 4; j++)
                acc[i][j] += a[i] * b[j];
    }

    #pragma unroll
    for (int i = 0; i < 4; i++) {
        int m = r0 + ty + 16 * i;
        #pragma unroll
        for (int j = 0; j < 4; j++) {
            int e = tx + 16 * j;
            dG[((size_t)m * HH + h) * EE + e] = acc[i][j];
        }
    }
}

// ---------------------------------------------------------------------------
// S1[bh][q][k] = sum_c Q_h[b,q,c] * KV_h[b,k,c]    (batched over bh, 64 blocks)
// 128x128 output, 256 threads, 8x8 per thread, c-tiles of 32
// ---------------------------------------------------------------------------
__global__ __launch_bounds__(256) void s1_kernel()
{
    __shared__ float Qs[128 * 32];   // [m][cc]
    __shared__ float Ks[128 * 33];   // [n][cc], padded

    const int bh = blockIdx.x;
    const int b  = bh >> 3, h = bh & 7;
    const int t  = threadIdx.x;
    const int tx = t & 15, ty = t >> 4;

    float acc[8][8] = {};

    for (int c0 = 0; c0 < 64; c0 += 32) {
        #pragma unroll
        for (int r = 0; r < 4; r++) {
            int idx = t + r * 256;       // 0..1023 float4
            int m   = idx >> 3;          // 0..127
            int c4  = (idx & 7) << 2;
            float4 q = *(const float4*)(dQ + (size_t)(b * LL + m) * DD + h * 64 + c0 + c4);
            *(float4*)(Qs + m * 32 + c4) = q;
            float4 k = *(const float4*)(dKV + (size_t)(b * LL + m) * DD + h * 64 + c0 + c4);
            Ks[m * 33 + c4 + 0] = k.x; Ks[m * 33 + c4 + 1] = k.y;
            Ks[m * 33 + c4 + 2] = k.z; Ks[m * 33 + c4 + 3] = k.w;
        }
        __syncthreads();

        #pragma unroll
        for (int cc = 0; cc < 32; cc++) {
            float a[8], bb[8];
            #pragma unroll
            for (int i = 0; i < 8; i++) a[i]  = Qs[(ty + 16 * i) * 32 + cc];
            #pragma unroll
            for (int j = 0; j < 8; j++) bb[j] = Ks[(tx + 16 * j) * 33 + cc];
            #pragma unroll
            for (int i = 0; i < 8; i++)
                #pragma unroll
                for (int j = 0; j < 8; j++)
                    acc[i][j] += a[i] * bb[j];
        }
        __syncthreads();
    }

    #pragma unroll
    for (int i = 0; i < 8; i++) {
        int m = ty + 16 * i;
        #pragma unroll
        for (int j = 0; j < 8; j++) {
            int n = tx + 16 * j;
            dS1[((size_t)bh * LL + m) * LL + n] = acc[i][j];
        }
    }
}

// ---------------------------------------------------------------------------
// Per (b,q): scores = (S1 + e·g)/8 -> leaky -> mask -> softmax -> alpha;
//            Wsum[e] = sum_k alpha_k * e[k][e].   1024 blocks x 128 threads.
// ---------------------------------------------------------------------------
__global__ __launch_bounds__(128) void softmax_kernel(
    const float* __restrict__ eptr, const int* __restrict__ adj)
{
    __shared__ float es[128 * 65];   // e tile [k][j], padded
    __shared__ float gs[64];
    __shared__ float sc[128];
    __shared__ float red[4];
    __shared__ float wtmp[128];

    const int bq = blockIdx.x;        // b*128 + q
    const int b  = bq >> 7, q = bq & 127;
    const int t  = threadIdx.x;
    const int lane = t & 31, warp = t >> 5;

    // load e[b,q,:,:]  (128x64 floats)
    #pragma unroll
    for (int r = 0; r < 16; r++) {
        int idx = t + r * 128;        // 0..2047 float4
        int k   = idx >> 4;
        int j4  = (idx & 15) << 2;
        float4 v = *(const float4*)(eptr + ((size_t)bq * LL + k) * EE + j4);
        es[k * 65 + j4 + 0] = v.x; es[k * 65 + j4 + 1] = v.y;
        es[k * 65 + j4 + 2] = v.z; es[k * 65 + j4 + 3] = v.w;
    }
    const int adjv = adj[(size_t)bq * LL + t];

    for (int h = 0; h < HH; h++) {
        __syncthreads();
        if (t < 64) gs[t] = dG[((size_t)bq * HH + h) * EE + t];
        __syncthreads();

        // score for k = t
        float dot = 0.f;
        #pragma unroll
        for (int j = 0; j < 64; j++) dot += es[t * 65 + j] * gs[j];
        float s = (dS1[(((size_t)(b * HH + h)) * LL + q) * LL + t] + dot) * 0.125f;
        s = (s > 0.f) ? s : 0.2f * s;
        if (adjv == 0) s = -1e9f;

        // row max
        float mx = s;
        #pragma unroll
        for (int o = 16; o > 0; o >>= 1) mx = fmaxf(mx, __shfl_xor_sync(0xffffffff, mx, o));
        if (lane == 0) red[warp] = mx;
        __syncthreads();
        mx = fmaxf(fmaxf(red[0], red[1]), fmaxf(red[2], red[3]));
        __syncthreads();

        float p = expf(s - mx);
        float su = p;
        #pragma unroll
        for (int o = 16; o > 0; o >>= 1) su += __shfl_xor_sync(0xffffffff, su, o);
        if (lane == 0) red[warp] = su;
        __syncthreads();
        float total = red[0] + red[1] + red[2] + red[3];
        float pk = p / total;
        sc[t] = pk;
        dALPHA[(((size_t)(b * HH + h)) * LL + q) * LL + t] = pk;
        __syncthreads();

        // Wsum: 2 threads per e
        {
            int ei = t & 63, half = t >> 6;
            float acc = 0.f;
            #pragma unroll
            for (int k = 0; k < 64; k++) {
                int kk = half * 64 + k;
                acc += sc[kk] * es[kk * 65 + ei];
            }
            wtmp[t] = acc;
            __syncthreads();
            if (t < 64)
                dWsum[(((size_t)(b * HH + h)) * LL + q) * EE + t] = wtmp[t] + wtmp[64 + t];
        }
    }
}

// ---------------------------------------------------------------------------
// ATTN[b,q,h*64+c] = alpha[bh,q,:] @ KV_h[b,:,c]  +  Wsum[bh,q,:] @ We_h[:,c]
// One 192-deep GEMM per (bh, m-half). grid (64,2), 256 threads, 4x4/thread.
// ---------------------------------------------------------------------------
__global__ __launch_bounds__(256) void attn_kernel(const float* __restrict__ We)
{
    __shared__ float As[64 * 32];   // [m][kk]
    __shared__ float Bs[32 * 64];   // [kk][n]

    const int bh = blockIdx.x, mh = blockIdx.y;
    const int b  = bh >> 3, h = bh & 7;
    const int t  = threadIdx.x;
    const int tx = t & 15, ty = t >> 4;

    float acc[4][4] = {};

    for (int k0 = 0; k0 < 192; k0 += 32) {
        // A tile (alpha for k<128, Wsum for k>=128)
        #pragma unroll
        for (int r = 0; r < 2; r++) {
            int idx = t + r * 256;
            int m   = idx >> 3;
            int k4  = (idx & 7) << 2;
            size_t row = (size_t)bh * LL + mh * 64 + m;
            float4 v;
            if (k0 < 128) v = *(const float4*)(dALPHA + row * LL + k0 + k4);
            else          v = *(const float4*)(dWsum  + row * EE + (k0 - 128) + k4);
            *(float4*)(As + m * 32 + k4) = v;
        }
        // B tile (KV rows for k<128, We rows for k>=128)
        #pragma unroll
        for (int r = 0; r < 2; r++) {
            int idx = t + r * 256;
            int kk  = idx >> 4;
            int n4  = (idx & 15) << 2;
            int kg  = k0 + kk;
            float4 v;
            if (kg < 128) v = *(const float4*)(dKV + (size_t)(b * LL + kg) * DD + h * 64 + n4);
            else          v = *(const float4*)(We + (size_t)(kg - 128) * DD + h * 64 + n4);
            *(float4*)(Bs + kk * 64 + n4) = v;
        }
        __syncthreads();

        #pragma unroll
        for (int kk = 0; kk < 32; kk++) {
            float a[4], bb[4];
            #pragma unroll
            for (int i = 0; i < 4; i++) a[i]  = As[(ty + 16 * i) * 32 + kk];
            #pragma unroll
            for (int j = 0; j < 4; j++) bb[j] = Bs[kk * 64 + tx + 16 * j];
            #pragma unroll
            for (int i = 0; i < 4; i++)
                #pragma unroll
                for (int j = 0; j < 4; j++)
                    acc[i][j] += a[i] * bb[j];
        }
        __syncthreads();
    }

    #pragma unroll
    for (int i = 0; i < 4; i++) {
        int m = mh * 64 + ty + 16 * i;
        #pragma unroll
        for (int j = 0; j < 4; j++) {
            int n = tx + 16 * j;
            dATTN[((size_t)b * LL + m) * DD + h * 64 + n] = acc[i][j];
        }
    }
}

// ---------------------------------------------------------------------------
// LayerNorm + ReLU per row of 512. 1024 blocks x 256 threads.
// ---------------------------------------------------------------------------
__global__ __launch_bounds__(256) void ln_kernel(
    const float* __restrict__ gamma, const float* __restrict__ beta,
    float* __restrict__ out)
{
    const int r = blockIdx.x;
    const int t = threadIdx.x;
    const int lane = t & 31, warp = t >> 5;

    float v0 = dFFN[(size_t)r * DD + t];
    float v1 = dFFN[(size_t)r * DD + 256 + t];
    float s  = v0 + v1;
    float sq = v0 * v0 + v1 * v1;

    __shared__ float rs[8], rq[8];
    __shared__ float mu_s, rstd_s;
    #pragma unroll
    for (int o = 16; o > 0; o >>= 1) {
        s  += __shfl_xor_sync(0xffffffff, s, o);
        sq += __shfl_xor_sync(0xffffffff, sq, o);
    }
    if (lane == 0) { rs[warp] = s; rq[warp] = sq; }
    __syncthreads();
    if (t == 0) {
        float S = 0.f, Q2 = 0.f;
        #pragma unroll
        for (int w = 0; w < 8; w++) { S += rs[w]; Q2 += rq[w]; }
        float mu  = S / 512.f;
        float var = Q2 / 512.f - mu * mu;
        mu_s = mu;
        rstd_s = rsqrtf(var + 1e-5f);
    }
    __syncthreads();
    float mu = mu_s, rstd = rstd_s;

    float y0 = (v0 - mu) * rstd * gamma[t]       + beta[t];
    float y1 = (v1 - mu) * rstd * gamma[256 + t] + beta[256 + t];
    out[(size_t)r * DD + t]       = fmaxf(y0, 0.f);
    out[(size_t)r * DD + 256 + t] = fmaxf(y1, 0.f);
}

// ---------------------------------------------------------------------------
extern "C" void kernel_launch(void* const* d_in, const int* in_sizes, int n_in,
                              void* d_out, int out_size)
{
    const float* x     = (const float*)d_in[0];
    const int*   adj   = (const int*)  d_in[1];
    const float* e     = (const float*)d_in[2];
    const float* Wq    = (const float*)d_in[3];
    const float* Wkv   = (const float*)d_in[4];
    const float* We    = (const float*)d_in[5];
    const float* Wf    = (const float*)d_in[6];
    const float* bf    = (const float*)d_in[7];
    const float* gamma = (const float*)d_in[8];
    const float* beta  = (const float*)d_in[9];
    float* out = (float*)d_out;

    float *pQ, *pKV, *pATTN, *pFFN;
    cudaGetSymbolAddress((void**)&pQ,    dQ);
    cudaGetSymbolAddress((void**)&pKV,   dKV);
    cudaGetSymbolAddress((void**)&pATTN, dATTN);
    cudaGetSymbolAddress((void**)&pFFN,  dFFN);

    // 1. Q = x@Wq, KV = x@Wkv (one launch, z selects)
    gemm64_kernel<<<dim3(DD/64, BL/64, 2), 256>>>(x, Wq, pQ, Wkv, pKV, nullptr,
                                                  BL, DD, DD);
    // 2. g = We_h^T q_h
    g_kernel<<<dim3(BL/64, HH), 256>>>(We);
    // 3. S1 = Q_h @ KV_h^T (batched)
    s1_kernel<<<BB*HH, 256>>>();
    // 4. softmax + alpha-weighted e reduction
    softmax_kernel<<<BL, 128>>>(e, adj);
    // 5. attention output (alpha@KV + Wsum@We_h)
    attn_kernel<<<dim3(BB*HH, 2), 256>>>(We);
    // 6. FFN GEMM with bias
    gemm64_kernel<<<dim3(DD/64, BL/64, 1), 256>>>(pATTN, Wf, pFFN, nullptr, nullptr,
                                                  bf, BL, DD, DD);
    // 7. LayerNorm + ReLU -> d_out
    ln_kernel<<<BL, 256>>>(gamma, beta, out);
}

// round 4
// speedup vs baseline: 1.3494x; 1.2879x over previous
#include <cuda_runtime.h>
#include <math.h>

#define BB 8
#define LL 128
#define DD 512
#define EE 64
#define HH 8
#define BL (BB*LL)   // 1024

typedef unsigned long long ull;

__device__ __forceinline__ void fma2(ull &acc, ull a, ull b) {
    asm("fma.rn.f32x2 %0, %1, %2, %0;" : "+l"(acc) : "l"(a), "l"(b));
}
__device__ __forceinline__ float fsum2(ull v) {
    float x, y;
    asm("mov.b64 {%0,%1}, %2;" : "=f"(x), "=f"(y) : "l"(v));
    return x + y;
}

// Scratch
__device__ float dQ[BL*DD];
__device__ float dKV[BL*DD];
__device__ float dG[BL*HH*EE];           // [bq][h][e]
__device__ float dS1[BB*HH*LL*LL];       // [bh][q][k]
__device__ float dALPHA[BB*HH*LL*LL];    // [bh][q][k]
__device__ float dWsum[BB*HH*LL*EE];     // [bh][q][e]
__device__ float dATTN[BL*DD];
__device__ float dFFN[BL*DD];

// ---------------------------------------------------------------------------
// f32x2 GEMM: 64x64 tile, 128 threads, frag 8m x 4n, K paired in smem stride 34.
// z selects (B0,C0)/(B1,C1).
// ---------------------------------------------------------------------------
__global__ __launch_bounds__(128) void gemm_f2(
    const float* __restrict__ A,
    const float* __restrict__ B0, float* __restrict__ C0,
    const float* __restrict__ B1, float* __restrict__ C1,
    const float* __restrict__ bias, int K, int N)
{
    __shared__ float As[64*34];    // [m][kk]
    __shared__ float Bt[64*34];    // [n][kk]

    const float* Bm = blockIdx.z ? B1 : B0;
    float*       Cm = blockIdx.z ? C1 : C0;

    const int t  = threadIdx.x;
    const int tx = t & 15, ty = t >> 4;           // ty 0..7
    const int m0 = blockIdx.y * 64, n0 = blockIdx.x * 64;

    ull acc[8][4] = {};

    for (int k0 = 0; k0 < K; k0 += 32) {
        // A tile 64x32 (k contiguous in source)
        #pragma unroll
        for (int r = 0; r < 4; r++) {
            int idx = t + r * 128;
            int m   = idx >> 3;
            int k4  = (idx & 7) << 2;
            float4 v = *(const float4*)(A + (size_t)(m0 + m) * K + k0 + k4);
            *(float2*)(As + m * 34 + k4)     = make_float2(v.x, v.y);
            *(float2*)(As + m * 34 + k4 + 2) = make_float2(v.z, v.w);
        }
        // B tile 32x64 -> transposed [n][kk], k-pairs interleaved
        #pragma unroll
        for (int r = 0; r < 2; r++) {
            int idx = t + r * 128;
            int kp  = idx >> 4;
            int n4  = (idx & 15) << 2;
            int kk  = kp * 2;
            float4 v0 = *(const float4*)(Bm + (size_t)(k0 + kk)     * N + n0 + n4);
            float4 v1 = *(const float4*)(Bm + (size_t)(k0 + kk + 1) * N + n0 + n4);
            *(float2*)(Bt + (n4 + 0) * 34 + kk) = make_float2(v0.x, v1.x);
            *(float2*)(Bt + (n4 + 1) * 34 + kk) = make_float2(v0.y, v1.y);
            *(float2*)(Bt + (n4 + 2) * 34 + kk) = make_float2(v0.z, v1.z);
            *(float2*)(Bt + (n4 + 3) * 34 + kk) = make_float2(v0.w, v1.w);
        }
        __syncthreads();

        #pragma unroll
        for (int kk = 0; kk < 32; kk += 2) {
            ull a[8], b[4];
            #pragma unroll
            for (int i = 0; i < 8; i++) a[i] = *(const ull*)(As + (ty * 8 + i) * 34 + kk);
            #pragma unroll
            for (int j = 0; j < 4; j++) b[j] = *(const ull*)(Bt + (tx + 16 * j) * 34 + kk);
            #pragma unroll
            for (int i = 0; i < 8; i++)
                #pragma unroll
                for (int j = 0; j < 4; j++)
                    fma2(acc[i][j], a[i], b[j]);
        }
        __syncthreads();
    }

    #pragma unroll
    for (int i = 0; i < 8; i++) {
        int m = m0 + ty * 8 + i;
        #pragma unroll
        for (int j = 0; j < 4; j++) {
            int n = n0 + tx + 16 * j;
            float v = fsum2(acc[i][j]);
            if (bias) v += bias[n];
            Cm[(size_t)m * N + n] = v;
        }
    }
}

// ---------------------------------------------------------------------------
// g[bq][h][e] = sum_c Q[bq, h*64+c] * We[e, h*64+c]   (scalar; small)
// ---------------------------------------------------------------------------
__global__ __launch_bounds__(256) void g_kernel(const float* __restrict__ We)
{
    __shared__ float Qs[64 * 65];
    __shared__ float Ws[64 * 65];

    const int t  = threadIdx.x;
    const int tx = t & 15, ty = t >> 4;
    const int r0 = blockIdx.x * 64;
    const int h  = blockIdx.y;

    #pragma unroll
    for (int r = 0; r < 4; r++) {
        int idx = t + r * 256;
        int m   = idx >> 4;
        int c4  = (idx & 15) << 2;
        float4 q = *(const float4*)(dQ + (size_t)(r0 + m) * DD + h * 64 + c4);
        Qs[m * 65 + c4 + 0] = q.x; Qs[m * 65 + c4 + 1] = q.y;
        Qs[m * 65 + c4 + 2] = q.z; Qs[m * 65 + c4 + 3] = q.w;
        float4 w = *(const float4*)(We + (size_t)m * DD + h * 64 + c4);
        Ws[m * 65 + c4 + 0] = w.x; Ws[m * 65 + c4 + 1] = w.y;
        Ws[m * 65 + c4 + 2] = w.z; Ws[m * 65 + c4 + 3] = w.w;
    }
    __syncthreads();

    float acc[4][4] = {};
    #pragma unroll
    for (int c = 0; c < 64; c++) {
        float a[4], b[4];
        #pragma unroll
        for (int i = 0; i < 4; i++) a[i] = Qs[(ty + 16 * i) * 65 + c];
        #pragma unroll
        for (int j = 0; j < 4; j++) b[j] = Ws[(tx + 16 * j) * 65 + c];
        #pragma unroll
        for (int i = 0; i < 4; i++)
            #pragma unroll
            for (int j = 0; j < 4; j++)
                acc[i][j] += a[i] * b[j];
    }

    #pragma unroll
    for (int i = 0; i < 4; i++) {
        int m = r0 + ty + 16 * i;
        #pragma unroll
        for (int j = 0; j < 4; j++)
            dG[((size_t)m * HH + h) * EE + tx + 16 * j] = acc[i][j];
    }
}

// ---------------------------------------------------------------------------
// S1: 64m x 128n tile per block, grid (64,2), 256 threads, frag 4m x 8n, f32x2
// ---------------------------------------------------------------------------
__global__ __launch_bounds__(256) void s1_f2()
{
    __shared__ float Qs[64 * 34];    // [m][cc]
    __shared__ float Ks[128 * 34];   // [n][cc]

    const int bh = blockIdx.x, mh = blockIdx.y;
    const int b  = bh >> 3, h = bh & 7;
    const int t  = threadIdx.x;
    const int tx = t & 15, ty = t >> 4;   // ty 0..15

    ull acc[4][8] = {};

    for (int c0 = 0; c0 < 64; c0 += 32) {
        #pragma unroll
        for (int r = 0; r < 2; r++) {
            int idx = t + r * 256;
            int m   = idx >> 3;
            int c4  = (idx & 7) << 2;
            float4 v = *(const float4*)(dQ + (size_t)(b * LL + mh * 64 + m) * DD + h * 64 + c0 + c4);
            *(float2*)(Qs + m * 34 + c4)     = make_float2(v.x, v.y);
            *(float2*)(Qs + m * 34 + c4 + 2) = make_float2(v.z, v.w);
        }
        #pragma unroll
        for (int r = 0; r < 4; r++) {
            int idx = t + r * 256;
            int n   = idx >> 3;
            int c4  = (idx & 7) << 2;
            float4 v = *(const float4*)(dKV + (size_t)(b * LL + n) * DD + h * 64 + c0 + c4);
            *(float2*)(Ks + n * 34 + c4)     = make_float2(v.x, v.y);
            *(float2*)(Ks + n * 34 + c4 + 2) = make_float2(v.z, v.w);
        }
        __syncthreads();

        #pragma unroll
        for (int cc = 0; cc < 32; cc += 2) {
            ull a[4], b2[8];
            #pragma unroll
            for (int i = 0; i < 4; i++) a[i]  = *(const ull*)(Qs + (ty * 4 + i) * 34 + cc);
            #pragma unroll
            for (int j = 0; j < 8; j++) b2[j] = *(const ull*)(Ks + (tx + 16 * j) * 34 + cc);
            #pragma unroll
            for (int i = 0; i < 4; i++)
                #pragma unroll
                for (int j = 0; j < 8; j++)
                    fma2(acc[i][j], a[i], b2[j]);
        }
        __syncthreads();
    }

    #pragma unroll
    for (int i = 0; i < 4; i++) {
        int m = mh * 64 + ty * 4 + i;
        #pragma unroll
        for (int j = 0; j < 8; j++)
            dS1[((size_t)bh * LL + m) * LL + tx + 16 * j] = fsum2(acc[i][j]);
    }
}

// ---------------------------------------------------------------------------
// Softmax: one block per (b,q); all 8 heads in a single pass.
// thread t owns key k=t. es read once (float4, conflict-free), g transposed,
// alpha transposed for the Wsum pass.
// ---------------------------------------------------------------------------
__global__ __launch_bounds__(128) void softmax2(
    const float* __restrict__ eptr, const int* __restrict__ adj)
{
    __shared__ float es[128 * 68];   // [k][j], float4-aligned, conflict-free both ways
    __shared__ float gT[64 * 12];    // [j][h]
    __shared__ float aT[128 * 12];   // [k][h]
    __shared__ float wred[64 * 8];   // [e][h] partial
    __shared__ float red[4][8];      // [warp][h]

    const int bq = blockIdx.x;
    const int b  = bq >> 7, q = bq & 127;
    const int t  = threadIdx.x;
    const int lane = t & 31, warp = t >> 5;

    // load e[b,q,:,:] 128x64
    const float* erow = eptr + (size_t)bq * LL * EE;
    #pragma unroll
    for (int r = 0; r < 16; r++) {
        int idx = t + r * 128;
        int k   = idx >> 4;
        int j4  = (idx & 15) << 2;
        float4 v = *(const float4*)(erow + k * EE + j4);
        *(float4*)(es + k * 68 + j4) = v;
    }
    // gT[j][h] = dG[bq][h][j]
    for (int i = t; i < 512; i += 128) {
        int h = i >> 6, j = i & 63;
        gT[j * 12 + h] = dG[(size_t)bq * 512 + i];
    }
    // S1 row for all heads, k=t
    float sv[8];
    #pragma unroll
    for (int h = 0; h < HH; h++)
        sv[h] = dS1[(((size_t)(b * HH + h)) * LL + q) * LL + t];
    const int adjv = adj[(size_t)bq * LL + t];
    __syncthreads();

    // dots: acc[h] = sum_j es[t][j] * gT[j][h]
    float acc[8] = {};
    #pragma unroll
    for (int j4 = 0; j4 < 16; j4++) {
        float4 ev = *(const float4*)(es + t * 68 + j4 * 4);
        float evv[4] = {ev.x, ev.y, ev.z, ev.w};
        #pragma unroll
        for (int jj = 0; jj < 4; jj++) {
            int j = j4 * 4 + jj;
            float4 ga = *(const float4*)(gT + j * 12);
            float4 gb = *(const float4*)(gT + j * 12 + 4);
            acc[0] += evv[jj] * ga.x; acc[1] += evv[jj] * ga.y;
            acc[2] += evv[jj] * ga.z; acc[3] += evv[jj] * ga.w;
            acc[4] += evv[jj] * gb.x; acc[5] += evv[jj] * gb.y;
            acc[6] += evv[jj] * gb.z; acc[7] += evv[jj] * gb.w;
        }
    }

    // scores -> leaky -> mask
    #pragma unroll
    for (int h = 0; h < HH; h++) {
        float s = (sv[h] + acc[h]) * 0.125f;
        s = (s > 0.f) ? s : 0.2f * s;
        if (adjv == 0) s = -1e9f;
        sv[h] = s;
    }

    // block max per head
    #pragma unroll
    for (int h = 0; h < HH; h++) {
        float m = sv[h];
        #pragma unroll
        for (int o = 16; o > 0; o >>= 1) m = fmaxf(m, __shfl_xor_sync(0xffffffffu, m, o));
        if (lane == 0) red[warp][h] = m;
    }
    __syncthreads();
    float p[8];
    #pragma unroll
    for (int h = 0; h < HH; h++) {
        float mx = fmaxf(fmaxf(red[0][h], red[1][h]), fmaxf(red[2][h], red[3][h]));
        p[h] = __expf(sv[h] - mx);
    }
    __syncthreads();
    // block sum per head
    #pragma unroll
    for (int h = 0; h < HH; h++) {
        float s = p[h];
        #pragma unroll
        for (int o = 16; o > 0; o >>= 1) s += __shfl_xor_sync(0xffffffffu, s, o);
        if (lane == 0) red[warp][h] = s;
    }
    __syncthreads();
    float al[8];
    #pragma unroll
    for (int h = 0; h < HH; h++) {
        float tot = red[0][h] + red[1][h] + red[2][h] + red[3][h];
        al[h] = p[h] / tot;
        dALPHA[(((size_t)(b * HH + h)) * LL + q) * LL + t] = al[h];
    }
    *(float4*)(aT + t * 12)     = make_float4(al[0], al[1], al[2], al[3]);
    *(float4*)(aT + t * 12 + 4) = make_float4(al[4], al[5], al[6], al[7]);
    __syncthreads();

    // Wsum[h][e] = sum_k al[h][k] * es[k][e]; thread -> (e, half of k)
    {
        int ei = t & 63, half = t >> 6;
        float w[8] = {};
        #pragma unroll 8
        for (int kk = 0; kk < 64; kk++) {
            int k = half * 64 + kk;
            float ev = es[k * 68 + ei];
            float4 a0 = *(const float4*)(aT + k * 12);
            float4 a1 = *(const float4*)(aT + k * 12 + 4);
            w[0] += ev * a0.x; w[1] += ev * a0.y; w[2] += ev * a0.z; w[3] += ev * a0.w;
            w[4] += ev * a1.x; w[5] += ev * a1.y; w[6] += ev * a1.z; w[7] += ev * a1.w;
        }
        if (half == 1) {
            *(float4*)(wred + ei * 8)     = make_float4(w[0], w[1], w[2], w[3]);
            *(float4*)(wred + ei * 8 + 4) = make_float4(w[4], w[5], w[6], w[7]);
        }
        __syncthreads();
        if (half == 0) {
            #pragma unroll
            for (int h = 0; h < HH; h++) {
                float v = w[h] + wred[ei * 8 + h];
                dWsum[(((size_t)(b * HH + h)) * LL + q) * EE + ei] = v;
            }
        }
    }
}

// ---------------------------------------------------------------------------
// ATTN = alpha@KV + Wsum@We_h : 64x64 tile, K=192 (128 alpha + 64 wsum), f32x2
// grid (64,2), 128 threads, frag 8m x 4n
// ---------------------------------------------------------------------------
__global__ __launch_bounds__(128) void attn_f2(const float* __restrict__ We)
{
    __shared__ float As[64 * 34];
    __shared__ float Bt[64 * 34];

    const int bh = blockIdx.x, mh = blockIdx.y;
    const int b  = bh >> 3, h = bh & 7;
    const int t  = threadIdx.x;
    const int tx = t & 15, ty = t >> 4;   // ty 0..7

    ull acc[8][4] = {};

    for (int k0 = 0; k0 < 192; k0 += 32) {
        // A tile
        #pragma unroll
        for (int r = 0; r < 4; r++) {
            int idx = t + r * 128;
            int m   = idx >> 3;
            int k4  = (idx & 7) << 2;
            size_t row = (size_t)bh * LL + mh * 64 + m;
            float4 v;
            if (k0 < 128) v = *(const float4*)(dALPHA + row * LL + k0 + k4);
            else          v = *(const float4*)(dWsum  + row * EE + (k0 - 128) + k4);
            *(float2*)(As + m * 34 + k4)     = make_float2(v.x, v.y);
            *(float2*)(As + m * 34 + k4 + 2) = make_float2(v.z, v.w);
        }
        // B tile transposed
        #pragma unroll
        for (int r = 0; r < 2; r++) {
            int idx = t + r * 128;
            int kp  = idx >> 4;
            int n4  = (idx & 15) << 2;
            int kk  = kp * 2;
            int kg  = k0 + kk;
            float4 v0, v1;
            if (kg < 128) {
                v0 = *(const float4*)(dKV + (size_t)(b * LL + kg)     * DD + h * 64 + n4);
                v1 = *(const float4*)(dKV + (size_t)(b * LL + kg + 1) * DD + h * 64 + n4);
            } else {
                v0 = *(const float4*)(We + (size_t)(kg - 128) * DD + h * 64 + n4);
                v1 = *(const float4*)(We + (size_t)(kg - 127) * DD + h * 64 + n4);
            }
            *(float2*)(Bt + (n4 + 0) * 34 + kk) = make_float2(v0.x, v1.x);
            *(float2*)(Bt + (n4 + 1) * 34 + kk) = make_float2(v0.y, v1.y);
            *(float2*)(Bt + (n4 + 2) * 34 + kk) = make_float2(v0.z, v1.z);
            *(float2*)(Bt + (n4 + 3) * 34 + kk) = make_float2(v0.w, v1.w);
        }
        __syncthreads();

        #pragma unroll
        for (int kk = 0; kk < 32; kk += 2) {
            ull a[8], b2[4];
            #pragma unroll
            for (int i = 0; i < 8; i++) a[i]  = *(const ull*)(As + (ty * 8 + i) * 34 + kk);
            #pragma unroll
            for (int j = 0; j < 4; j++) b2[j] = *(const ull*)(Bt + (tx + 16 * j) * 34 + kk);
            #pragma unroll
            for (int i = 0; i < 8; i++)
                #pragma unroll
                for (int j = 0; j < 4; j++)
                    fma2(acc[i][j], a[i], b2[j]);
        }
        __syncthreads();
    }

    #pragma unroll
    for (int i = 0; i < 8; i++) {
        int m = mh * 64 + ty * 8 + i;
        #pragma unroll
        for (int j = 0; j < 4; j++) {
            int n = tx + 16 * j;
            dATTN[((size_t)(b * LL) + m) * DD + h * 64 + n] = fsum2(acc[i][j]);
        }
    }
}

// ---------------------------------------------------------------------------
// LayerNorm + ReLU per row of 512
// ---------------------------------------------------------------------------
__global__ __launch_bounds__(256) void ln_kernel(
    const float* __restrict__ gamma, const float* __restrict__ beta,
    float* __restrict__ out)
{
    const int r = blockIdx.x;
    const int t = threadIdx.x;
    const int lane = t & 31, warp = t >> 5;

    float v0 = dFFN[(size_t)r * DD + t];
    float v1 = dFFN[(size_t)r * DD + 256 + t];
    float s  = v0 + v1;
    float sq = v0 * v0 + v1 * v1;

    __shared__ float rs[8], rq[8];
    __shared__ float mu_s, rstd_s;
    #pragma unroll
    for (int o = 16; o > 0; o >>= 1) {
        s  += __shfl_xor_sync(0xffffffffu, s, o);
        sq += __shfl_xor_sync(0xffffffffu, sq, o);
    }
    if (lane == 0) { rs[warp] = s; rq[warp] = sq; }
    __syncthreads();
    if (t == 0) {
        float S = 0.f, Q2 = 0.f;
        #pragma unroll
        for (int w = 0; w < 8; w++) { S += rs[w]; Q2 += rq[w]; }
        float mu  = S / 512.f;
        float var = Q2 / 512.f - mu * mu;
        mu_s = mu;
        rstd_s = rsqrtf(var + 1e-5f);
    }
    __syncthreads();
    float mu = mu_s, rstd = rstd_s;

    float y0 = (v0 - mu) * rstd * gamma[t]       + beta[t];
    float y1 = (v1 - mu) * rstd * gamma[256 + t] + beta[256 + t];
    out[(size_t)r * DD + t]       = fmaxf(y0, 0.f);
    out[(size_t)r * DD + 256 + t] = fmaxf(y1, 0.f);
}

// ---------------------------------------------------------------------------
extern "C" void kernel_launch(void* const* d_in, const int* in_sizes, int n_in,
                              void* d_out, int out_size)
{
    const float* x     = (const float*)d_in[0];
    const int*   adj   = (const int*)  d_in[1];
    const float* e     = (const float*)d_in[2];
    const float* Wq    = (const float*)d_in[3];
    const float* Wkv   = (const float*)d_in[4];
    const float* We    = (const float*)d_in[5];
    const float* Wf    = (const float*)d_in[6];
    const float* bf    = (const float*)d_in[7];
    const float* gamma = (const float*)d_in[8];
    const float* beta  = (const float*)d_in[9];
    float* out = (float*)d_out;

    float *pQ, *pKV, *pATTN, *pFFN;
    cudaGetSymbolAddress((void**)&pQ,    dQ);
    cudaGetSymbolAddress((void**)&pKV,   dKV);
    cudaGetSymbolAddress((void**)&pATTN, dATTN);
    cudaGetSymbolAddress((void**)&pFFN,  dFFN);

    // 1. Q = x@Wq, KV = x@Wkv
    gemm_f2<<<dim3(DD/64, BL/64, 2), 128>>>(x, Wq, pQ, Wkv, pKV, nullptr, DD, DD);
    // 2. g = We_h^T q_h
    g_kernel<<<dim3(BL/64, HH), 256>>>(We);
    // 3. S1 = Q_h @ KV_h^T
    s1_f2<<<dim3(BB*HH, 2), 256>>>();
    // 4. softmax + alpha-weighted e reduction (all heads in one pass)
    softmax2<<<BL, 128>>>(e, adj);
    // 5. attention output
    attn_f2<<<dim3(BB*HH, 2), 128>>>(We);
    // 6. FFN GEMM with bias
    gemm_f2<<<dim3(DD/64, BL/64, 1), 128>>>(pATTN, Wf, pFFN, nullptr, nullptr, bf, DD, DD);
    // 7. LayerNorm + ReLU
    ln_kernel<<<BL, 256>>>(gamma, beta, out);
}